// round 1
// baseline (speedup 1.0000x reference)
#include <cuda_runtime.h>
#include <cstdint>

#define N_NODES 50000
#define N_EDGES 800000
#define D       128
#define NL      3
#define BN_EPS  1e-5f

// ---------------- scratch (no allocations allowed) ----------------
__device__ float g_h[(size_t)N_NODES * D];     // dinv[row]-scaled linear output
__device__ float g_agg[(size_t)N_NODES * D];   // scatter accumulator
__device__ float g_deg[N_NODES];
__device__ float g_dinv[N_NODES];
__device__ float g_stats[2 * D];               // col sums / col sumsq
__device__ float g_bn[2 * D];                  // scale / shift
__device__ int   g_is64;

// ---------------- edge index dtype sniffing ----------------
// Reference declares int64 but JAX without x64 silently emits int32.
// If the data is int32, the high 32 bits of the first 64-bit words are
// random node indices (zero w.p. 1/50000 each) -> 32 samples decide it.
__global__ void k_detect(const unsigned long long* __restrict__ ei) {
    unsigned long long v = ei[threadIdx.x];
    int big = (v >> 32) != 0ull;
    unsigned mask = __ballot_sync(0xffffffffu, big);
    if (threadIdx.x == 0) g_is64 = (mask == 0u) ? 1 : 0;
}

__device__ __forceinline__ void edge_rc(const void* ei, int is64, int e, int& r, int& c) {
    if (is64) {
        const long long* p = (const long long*)ei;
        r = (int)p[e];
        c = (int)p[N_EDGES + e];
    } else {
        const int* p = (const int*)ei;
        r = p[e];
        c = p[N_EDGES + e];
    }
}

__device__ __forceinline__ int edge_r(const void* ei, int is64, int e) {
    if (is64) return (int)((const long long*)ei)[e];
    return ((const int*)ei)[e];
}

// ---------------- degree / dinv ----------------
__global__ void k_zero_deg() {
    for (int i = blockIdx.x * blockDim.x + threadIdx.x; i < N_NODES;
         i += gridDim.x * blockDim.x)
        g_deg[i] = 0.0f;
}

__global__ void k_deg(const void* __restrict__ ei) {
    int is64 = g_is64;
    for (int e = blockIdx.x * blockDim.x + threadIdx.x; e < N_EDGES;
         e += gridDim.x * blockDim.x) {
        int r = edge_r(ei, is64, e);
        atomicAdd(&g_deg[r], 1.0f);
    }
}

__global__ void k_dinv() {
    for (int i = blockIdx.x * blockDim.x + threadIdx.x; i < N_NODES;
         i += gridDim.x * blockDim.x) {
        float d = g_deg[i];
        g_dinv[i] = (d > 0.0f) ? rsqrtf(d) : 0.0f;
    }
}

// ---------------- GEMM: h = (x @ W^T + b) * dinv[row]; also zero agg ----------------
// Block: 64 rows x 128 cols, 256 threads, each thread 8 rows x 4 cols.
// W transposed into shared (k-major, stride 132 floats for alignment),
// x tile transposed into shared (k-major, stride 68 floats).
__global__ void k_gemm(const float* __restrict__ x, const float* __restrict__ W,
                       const float* __restrict__ bvec) {
    extern __shared__ float sm[];
    float* Wt = sm;                 // 128 * 132
    float* xs = sm + 128 * 132;     // 128 * 68

    const int tid  = threadIdx.x;
    const int row0 = blockIdx.x * 64;

    // load W transposed: Wt[k*132 + c] = W[c*128 + k]
    for (int i = tid; i < 128 * 128; i += 256) {
        int c = i >> 7, k = i & 127;
        Wt[k * 132 + c] = W[i];
    }
    // load x tile transposed: xs[k*68 + r] = x[row0+r][k]
    for (int i = tid; i < 64 * 32; i += 256) {
        int r = i >> 5, kq = i & 31;
        int gr = row0 + r;
        float4 v = (gr < N_NODES) ? *(const float4*)&x[(size_t)gr * D + kq * 4]
                                  : make_float4(0.f, 0.f, 0.f, 0.f);
        xs[(kq * 4 + 0) * 68 + r] = v.x;
        xs[(kq * 4 + 1) * 68 + r] = v.y;
        xs[(kq * 4 + 2) * 68 + r] = v.z;
        xs[(kq * 4 + 3) * 68 + r] = v.w;
    }
    if (blockIdx.x == 0) g_stats[tid] = 0.0f;  // 256 threads cover 2*D
    __syncthreads();

    const int tx = tid & 31;   // col group: cols 4*tx .. 4*tx+3
    const int ty = tid >> 5;   // row group: rows ty*8 .. ty*8+7

    float4 bv = *(const float4*)&bvec[4 * tx];
    float4 acc[8];
#pragma unroll
    for (int rr = 0; rr < 8; rr++) acc[rr] = bv;

#pragma unroll 8
    for (int k = 0; k < 128; k++) {
        float4 w  = *(float4*)&Wt[k * 132 + 4 * tx];
        float4 xa = *(float4*)&xs[k * 68 + 8 * ty];
        float4 xb = *(float4*)&xs[k * 68 + 8 * ty + 4];
        float xr[8] = {xa.x, xa.y, xa.z, xa.w, xb.x, xb.y, xb.z, xb.w};
#pragma unroll
        for (int rr = 0; rr < 8; rr++) {
            acc[rr].x += xr[rr] * w.x;
            acc[rr].y += xr[rr] * w.y;
            acc[rr].z += xr[rr] * w.z;
            acc[rr].w += xr[rr] * w.w;
        }
    }

#pragma unroll
    for (int rr = 0; rr < 8; rr++) {
        int r = row0 + ty * 8 + rr;
        if (r < N_NODES) {
            float s = g_dinv[r];
            float4 o;
            o.x = acc[rr].x * s;
            o.y = acc[rr].y * s;
            o.z = acc[rr].z * s;
            o.w = acc[rr].w * s;
            *(float4*)&g_h[(size_t)r * D + 4 * tx]   = o;
            *(float4*)&g_agg[(size_t)r * D + 4 * tx] = make_float4(0.f, 0.f, 0.f, 0.f);
        }
    }
}

// ---------------- scatter: agg[col] += h_scaled[row] (one warp per edge) ----------------
__global__ void k_scatter(const void* __restrict__ ei) {
    const int is64 = g_is64;
    const int lane = threadIdx.x & 31;
    const int gw   = blockIdx.x * (blockDim.x >> 5) + (threadIdx.x >> 5);
    const int nw   = gridDim.x * (blockDim.x >> 5);
    const float4* hp = (const float4*)g_h;

    for (int e = gw; e < N_EDGES; e += nw) {
        int r, c;
        edge_rc(ei, is64, e, r, c);
        float4 v = hp[r * 32 + lane];
        float* dst = &g_agg[(size_t)c * D + lane * 4];
        asm volatile("red.global.add.v4.f32 [%0], {%1,%2,%3,%4};"
                     :: "l"(dst), "f"(v.x), "f"(v.y), "f"(v.z), "f"(v.w)
                     : "memory");
    }
}

// ---------------- BN stats: per-column sum & sumsq of dinv[col]*agg ----------------
__global__ void k_stats() {
    int col = threadIdx.x;  // 128 threads
    float s = 0.f, q = 0.f;
    for (int r = blockIdx.x; r < N_NODES; r += gridDim.x) {
        float v = g_agg[(size_t)r * D + col] * g_dinv[r];
        s += v;
        q += v * v;
    }
    atomicAdd(&g_stats[col], s);
    atomicAdd(&g_stats[D + col], q);
}

__global__ void k_bnfinal(const float* __restrict__ gamma, const float* __restrict__ beta) {
    int c = threadIdx.x;
    const float inv_n = 1.0f / (float)N_NODES;
    float mu  = g_stats[c] * inv_n;
    float var = g_stats[D + c] * inv_n - mu * mu;
    float sc  = gamma[c] * rsqrtf(var + BN_EPS);
    g_bn[c]     = sc;
    g_bn[D + c] = beta[c] - mu * sc;
}

// ---------------- apply: x_new = x + relu(agg*dinv*scale + shift) ----------------
__global__ void k_apply(const float* __restrict__ xsrc, float* __restrict__ xdst) {
    int i = blockIdx.x * blockDim.x + threadIdx.x;  // over N*D/4 float4s
    if (i >= N_NODES * 32) return;
    int r  = i >> 5;
    int cq = i & 31;
    float s   = g_dinv[r];
    float4 a  = ((const float4*)g_agg)[i];
    float4 xv = ((const float4*)xsrc)[i];
    float4 sc = ((const float4*)g_bn)[cq];
    float4 sh = ((const float4*)(g_bn + D))[cq];
    float4 o;
    o.x = xv.x + fmaxf(fmaf(a.x * s, sc.x, sh.x), 0.f);
    o.y = xv.y + fmaxf(fmaf(a.y * s, sc.y, sh.y), 0.f);
    o.z = xv.z + fmaxf(fmaf(a.z * s, sc.z, sh.z), 0.f);
    o.w = xv.w + fmaxf(fmaf(a.w * s, sc.w, sh.w), 0.f);
    ((float4*)xdst)[i] = o;
}

// ---------------- launch ----------------
extern "C" void kernel_launch(void* const* d_in, const int* in_sizes, int n_in,
                              void* d_out, int out_size) {
    const float* x     = (const float*)d_in[0];
    const void*  ei    = d_in[1];
    const float* W     = (const float*)d_in[2];
    const float* bvec  = (const float*)d_in[3];
    const float* gamma = (const float*)d_in[4];
    const float* beta  = (const float*)d_in[5];
    float* out = (float*)d_out;

    const size_t smem = (size_t)(128 * 132 + 128 * 68) * sizeof(float);  // 100 KB
    cudaFuncSetAttribute(k_gemm, cudaFuncAttributeMaxDynamicSharedMemorySize, (int)smem);

    k_detect<<<1, 32>>>((const unsigned long long*)ei);
    k_zero_deg<<<128, 256>>>();
    k_deg<<<1024, 256>>>(ei);
    k_dinv<<<128, 256>>>();

    const float* xin = x;
    const int gemm_blocks  = (N_NODES + 63) / 64;           // 782
    const int apply_blocks = (N_NODES * 32 + 255) / 256;    // 6250

    for (int l = 0; l < NL; l++) {
        k_gemm<<<gemm_blocks, 256, smem>>>(xin, W + (size_t)l * D * D, bvec + l * D);
        k_scatter<<<4096, 256>>>(ei);
        k_stats<<<512, 128>>>();
        k_bnfinal<<<1, 128>>>(gamma + l * D, beta + l * D);
        k_apply<<<apply_blocks, 256>>>(xin, out);
        xin = out;
    }
}

// round 2
// speedup vs baseline: 1.4560x; 1.4560x over previous
#include <cuda_runtime.h>
#include <cstdint>

#define N_NODES 50000
#define N_EDGES 800000
#define D       128
#define NL      3
#define BN_EPS  1e-5f
#define SCAN_NB 196   // ceil(50000/256)

// ---------------- scratch (no allocations allowed) ----------------
__device__ float g_h[(size_t)N_NODES * D];     // dinv[row]-scaled linear output
__device__ float g_agg[(size_t)N_NODES * D];   // gathered + dinv[col]-scaled
__device__ float g_dinv[N_NODES];
__device__ int   g_degI[N_NODES];              // out-degree (over row)
__device__ int   g_colcnt[N_NODES];            // in-degree (over col) for CSR
__device__ int   g_offsets[N_NODES + 1];
__device__ int   g_cursor[N_NODES];
__device__ int   g_erow[N_EDGES];              // CSR payload: source row per edge
__device__ int   g_blocksum[SCAN_NB];
__device__ float g_stats[2 * D];               // col sums / col sumsq
__device__ float g_bn[2 * D];                  // scale / shift
__device__ int   g_is64;

// ---------------- edge index dtype sniffing ----------------
// Reference declares int64 but JAX without x64 silently emits int32.
__global__ void k_detect(const unsigned long long* __restrict__ ei) {
    unsigned long long v = ei[threadIdx.x];
    int big = (v >> 32) != 0ull;
    unsigned mask = __ballot_sync(0xffffffffu, big);
    if (threadIdx.x == 0) g_is64 = (mask == 0u) ? 1 : 0;
}

__device__ __forceinline__ void edge_rc(const void* ei, int is64, int e, int& r, int& c) {
    if (is64) {
        const long long* p = (const long long*)ei;
        r = (int)p[e];
        c = (int)p[N_EDGES + e];
    } else {
        const int* p = (const int*)ei;
        r = p[e];
        c = p[N_EDGES + e];
    }
}

// ---------------- preprocessing ----------------
__global__ void k_prezero() {
    for (int i = blockIdx.x * blockDim.x + threadIdx.x; i < N_NODES;
         i += gridDim.x * blockDim.x) {
        g_degI[i] = 0;
        g_colcnt[i] = 0;
    }
}

__global__ void k_hist(const void* __restrict__ ei) {
    int is64 = g_is64;
    for (int e = blockIdx.x * blockDim.x + threadIdx.x; e < N_EDGES;
         e += gridDim.x * blockDim.x) {
        int r, c;
        edge_rc(ei, is64, e, r, c);
        atomicAdd(&g_degI[r], 1);
        atomicAdd(&g_colcnt[c], 1);
    }
}

__global__ void k_dinv() {
    for (int i = blockIdx.x * blockDim.x + threadIdx.x; i < N_NODES;
         i += gridDim.x * blockDim.x) {
        int d = g_degI[i];
        g_dinv[i] = (d > 0) ? rsqrtf((float)d) : 0.0f;
    }
}

// exclusive scan of g_colcnt -> g_offsets (3 stages)
__global__ void k_scan1() {
    __shared__ int s[256];
    int tid = threadIdx.x;
    int i = blockIdx.x * 256 + tid;
    int v = (i < N_NODES) ? g_colcnt[i] : 0;
    s[tid] = v;
    __syncthreads();
    for (int off = 1; off < 256; off <<= 1) {
        int t = (tid >= off) ? s[tid - off] : 0;
        __syncthreads();
        if (tid >= off) s[tid] += t;
        __syncthreads();
    }
    if (i < N_NODES) g_offsets[i] = s[tid] - v;  // exclusive
    if (tid == 255) g_blocksum[blockIdx.x] = s[255];
}

__global__ void k_scan2() {
    if (threadIdx.x == 0) {
        int run = 0;
        for (int b = 0; b < SCAN_NB; b++) {
            int t = g_blocksum[b];
            g_blocksum[b] = run;
            run += t;
        }
    }
}

__global__ void k_scan3() {
    int i = blockIdx.x * blockDim.x + threadIdx.x;
    if (i < N_NODES) {
        int o = g_offsets[i] + g_blocksum[i >> 8];
        g_offsets[i] = o;
        g_cursor[i] = o;
    }
    if (i == 0) g_offsets[N_NODES] = N_EDGES;
}

__global__ void k_fill(const void* __restrict__ ei) {
    int is64 = g_is64;
    for (int e = blockIdx.x * blockDim.x + threadIdx.x; e < N_EDGES;
         e += gridDim.x * blockDim.x) {
        int r, c;
        edge_rc(ei, is64, e, r, c);
        int p = atomicAdd(&g_cursor[c], 1);
        g_erow[p] = r;
    }
}

// ---------------- GEMM: h = (x @ W^T + b) * dinv[row] ----------------
// Block: 64 rows x 128 cols, 256 threads, each thread 8 rows x 4 cols.
__global__ void k_gemm(const float* __restrict__ x, const float* __restrict__ W,
                       const float* __restrict__ bvec) {
    extern __shared__ float sm[];
    float* Wt = sm;                 // 128 * 132
    float* xs = sm + 128 * 132;     // 128 * 68

    const int tid  = threadIdx.x;
    const int row0 = blockIdx.x * 64;

    for (int i = tid; i < 128 * 128; i += 256) {
        int c = i >> 7, k = i & 127;
        Wt[k * 132 + c] = W[i];
    }
    for (int i = tid; i < 64 * 32; i += 256) {
        int r = i >> 5, kq = i & 31;
        int gr = row0 + r;
        float4 v = (gr < N_NODES) ? *(const float4*)&x[(size_t)gr * D + kq * 4]
                                  : make_float4(0.f, 0.f, 0.f, 0.f);
        xs[(kq * 4 + 0) * 68 + r] = v.x;
        xs[(kq * 4 + 1) * 68 + r] = v.y;
        xs[(kq * 4 + 2) * 68 + r] = v.z;
        xs[(kq * 4 + 3) * 68 + r] = v.w;
    }
    if (blockIdx.x == 0) g_stats[tid] = 0.0f;  // zero stats for this layer
    __syncthreads();

    const int tx = tid & 31;
    const int ty = tid >> 5;

    float4 bv = *(const float4*)&bvec[4 * tx];
    float4 acc[8];
#pragma unroll
    for (int rr = 0; rr < 8; rr++) acc[rr] = bv;

#pragma unroll 8
    for (int k = 0; k < 128; k++) {
        float4 w  = *(float4*)&Wt[k * 132 + 4 * tx];
        float4 xa = *(float4*)&xs[k * 68 + 8 * ty];
        float4 xb = *(float4*)&xs[k * 68 + 8 * ty + 4];
        float xr[8] = {xa.x, xa.y, xa.z, xa.w, xb.x, xb.y, xb.z, xb.w};
#pragma unroll
        for (int rr = 0; rr < 8; rr++) {
            acc[rr].x += xr[rr] * w.x;
            acc[rr].y += xr[rr] * w.y;
            acc[rr].z += xr[rr] * w.z;
            acc[rr].w += xr[rr] * w.w;
        }
    }

#pragma unroll
    for (int rr = 0; rr < 8; rr++) {
        int r = row0 + ty * 8 + rr;
        if (r < N_NODES) {
            float s = g_dinv[r];
            float4 o;
            o.x = acc[rr].x * s;
            o.y = acc[rr].y * s;
            o.z = acc[rr].z * s;
            o.w = acc[rr].w * s;
            *(float4*)&g_h[(size_t)r * D + 4 * tx] = o;
        }
    }
}

// ---------------- gather: agg[n] = dinv[n] * sum_{e: col=n} h[row_e]; fused BN stats ----------------
__global__ void k_gather() {
    const int lane = threadIdx.x & 31;
    const int warp = threadIdx.x >> 5;
    const int gw   = blockIdx.x * 8 + warp;
    const int nw   = gridDim.x * 8;
    const float4* hp = (const float4*)g_h;
    float4* ap = (float4*)g_agg;

    float s0 = 0.f, s1 = 0.f, s2 = 0.f, s3 = 0.f;
    float q0 = 0.f, q1 = 0.f, q2 = 0.f, q3 = 0.f;

    for (int node = gw; node < N_NODES; node += nw) {
        int st = g_offsets[node];
        int en = g_offsets[node + 1];
        float4 acc = make_float4(0.f, 0.f, 0.f, 0.f);
        for (int i = st; i < en; i += 32) {
            int idx = 0;
            if (i + lane < en) idx = g_erow[i + lane];
            int n = min(32, en - i);
#pragma unroll 4
            for (int j = 0; j < n; j++) {
                int r = __shfl_sync(0xffffffffu, idx, j);
                float4 v = hp[r * 32 + lane];
                acc.x += v.x; acc.y += v.y; acc.z += v.z; acc.w += v.w;
            }
        }
        float dc = g_dinv[node];
        acc.x *= dc; acc.y *= dc; acc.z *= dc; acc.w *= dc;
        ap[node * 32 + lane] = acc;
        s0 += acc.x; s1 += acc.y; s2 += acc.z; s3 += acc.w;
        q0 += acc.x * acc.x; q1 += acc.y * acc.y;
        q2 += acc.z * acc.z; q3 += acc.w * acc.w;
    }

    // block-level stat reduction: shared atomics (degree-8 conflicts), then global
    __shared__ float ssum[128], ssq[128];
    if (threadIdx.x < 128) { ssum[threadIdx.x] = 0.f; ssq[threadIdx.x] = 0.f; }
    __syncthreads();
    int c = lane * 4;
    atomicAdd(&ssum[c + 0], s0); atomicAdd(&ssum[c + 1], s1);
    atomicAdd(&ssum[c + 2], s2); atomicAdd(&ssum[c + 3], s3);
    atomicAdd(&ssq[c + 0], q0); atomicAdd(&ssq[c + 1], q1);
    atomicAdd(&ssq[c + 2], q2); atomicAdd(&ssq[c + 3], q3);
    __syncthreads();
    if (threadIdx.x < 128) {
        atomicAdd(&g_stats[threadIdx.x], ssum[threadIdx.x]);
        atomicAdd(&g_stats[D + threadIdx.x], ssq[threadIdx.x]);
    }
}

__global__ void k_bnfinal(const float* __restrict__ gamma, const float* __restrict__ beta) {
    int c = threadIdx.x;
    const float inv_n = 1.0f / (float)N_NODES;
    float mu  = g_stats[c] * inv_n;
    float var = g_stats[D + c] * inv_n - mu * mu;
    float sc  = gamma[c] * rsqrtf(var + BN_EPS);
    g_bn[c]     = sc;
    g_bn[D + c] = beta[c] - mu * sc;
}

// ---------------- apply: x_new = x + relu(agg*scale + shift) ----------------
__global__ void k_apply(const float* __restrict__ xsrc, float* __restrict__ xdst) {
    int i = blockIdx.x * blockDim.x + threadIdx.x;  // over N*D/4 float4s
    if (i >= N_NODES * 32) return;
    int cq = i & 31;
    float4 a  = ((const float4*)g_agg)[i];
    float4 xv = ((const float4*)xsrc)[i];
    float4 sc = ((const float4*)g_bn)[cq];
    float4 sh = ((const float4*)(g_bn + D))[cq];
    float4 o;
    o.x = xv.x + fmaxf(fmaf(a.x, sc.x, sh.x), 0.f);
    o.y = xv.y + fmaxf(fmaf(a.y, sc.y, sh.y), 0.f);
    o.z = xv.z + fmaxf(fmaf(a.z, sc.z, sh.z), 0.f);
    o.w = xv.w + fmaxf(fmaf(a.w, sc.w, sh.w), 0.f);
    ((float4*)xdst)[i] = o;
}

// ---------------- launch ----------------
extern "C" void kernel_launch(void* const* d_in, const int* in_sizes, int n_in,
                              void* d_out, int out_size) {
    const float* x     = (const float*)d_in[0];
    const void*  ei    = d_in[1];
    const float* W     = (const float*)d_in[2];
    const float* bvec  = (const float*)d_in[3];
    const float* gamma = (const float*)d_in[4];
    const float* beta  = (const float*)d_in[5];
    float* out = (float*)d_out;

    const size_t smem = (size_t)(128 * 132 + 128 * 68) * sizeof(float);  // 100 KB
    cudaFuncSetAttribute(k_gemm, cudaFuncAttributeMaxDynamicSharedMemorySize, (int)smem);

    // preprocessing: dtype detect, degrees, dinv, CSR build
    k_detect<<<1, 32>>>((const unsigned long long*)ei);
    k_prezero<<<128, 256>>>();
    k_hist<<<1024, 256>>>(ei);
    k_dinv<<<128, 256>>>();
    k_scan1<<<SCAN_NB, 256>>>();
    k_scan2<<<1, 32>>>();
    k_scan3<<<(N_NODES + 255) / 256, 256>>>();
    k_fill<<<1024, 256>>>(ei);

    const float* xin = x;
    const int gemm_blocks  = (N_NODES + 63) / 64;           // 782
    const int apply_blocks = (N_NODES * 32 + 255) / 256;    // 6250

    for (int l = 0; l < NL; l++) {
        k_gemm<<<gemm_blocks, 256, smem>>>(xin, W + (size_t)l * D * D, bvec + l * D);
        k_gather<<<512, 256>>>();
        k_bnfinal<<<1, 128>>>(gamma + l * D, beta + l * D);
        k_apply<<<apply_blocks, 256>>>(xin, out);
        xin = out;
    }
}

// round 4
// speedup vs baseline: 1.4694x; 1.0092x over previous
#include <cuda_runtime.h>
#include <cuda_fp16.h>
#include <cstdint>

#define N_NODES 50000
#define N_EDGES 800000
#define D       128
#define NL      3
#define BN_EPS  1e-5f
#define SCAN_NB 196   // ceil(50000/256)

// ---------------- scratch (no allocations allowed) ----------------
// h stored as fp16, packed 4 cols per uint2 (8B aligned by type)
__device__ uint2  g_h[(size_t)N_NODES * 32];
__device__ float  g_agg[(size_t)N_NODES * D];  // gathered + dinv[col]-scaled (fp32)
__device__ float  g_dinv[N_NODES];
__device__ int    g_degI[N_NODES];             // out-degree (over row)
__device__ int    g_colcnt[N_NODES];           // in-degree (over col) for CSR
__device__ int    g_offsets[N_NODES + 1];
__device__ int    g_cursor[N_NODES];
__device__ int    g_erow[N_EDGES];             // CSR payload: source row per edge
__device__ int    g_blocksum[SCAN_NB];
__device__ float  g_stats[2 * D];              // col sums / col sumsq
__device__ float  g_bn[2 * D];                 // scale / shift
__device__ int    g_is64;

// ---------------- prezero + edge dtype sniffing (fused) ----------------
// Reference declares int64 but JAX without x64 silently emits int32: if data
// is int32, the high words of the first 32 long longs are random node ids
// (each zero w.p. 1/50000), so 32 samples decide deterministically.
__global__ void k_pre(const unsigned long long* __restrict__ ei) {
    for (int i = blockIdx.x * blockDim.x + threadIdx.x; i < N_NODES;
         i += gridDim.x * blockDim.x) {
        g_degI[i] = 0;
        g_colcnt[i] = 0;
    }
    if (blockIdx.x == 0 && threadIdx.x < 32) {
        unsigned long long v = ei[threadIdx.x];
        int big = (v >> 32) != 0ull;
        unsigned mask = __ballot_sync(0xffffffffu, big);
        if (threadIdx.x == 0) g_is64 = (mask == 0u) ? 1 : 0;
    }
}

__device__ __forceinline__ void edge_rc(const void* ei, int is64, int e, int& r, int& c) {
    if (is64) {
        const long long* p = (const long long*)ei;
        r = (int)p[e];
        c = (int)p[N_EDGES + e];
    } else {
        const int* p = (const int*)ei;
        r = p[e];
        c = p[N_EDGES + e];
    }
}

__global__ void k_hist(const void* __restrict__ ei) {
    int is64 = g_is64;
    for (int e = blockIdx.x * blockDim.x + threadIdx.x; e < N_EDGES;
         e += gridDim.x * blockDim.x) {
        int r, c;
        edge_rc(ei, is64, e, r, c);
        atomicAdd(&g_degI[r], 1);
        atomicAdd(&g_colcnt[c], 1);
    }
}

// exclusive scan of g_colcnt -> g_offsets (3 stages); dinv fused into stage 3
__global__ void k_scan1() {
    __shared__ int s[256];
    int tid = threadIdx.x;
    int i = blockIdx.x * 256 + tid;
    int v = (i < N_NODES) ? g_colcnt[i] : 0;
    s[tid] = v;
    __syncthreads();
    for (int off = 1; off < 256; off <<= 1) {
        int t = (tid >= off) ? s[tid - off] : 0;
        __syncthreads();
        if (tid >= off) s[tid] += t;
        __syncthreads();
    }
    if (i < N_NODES) g_offsets[i] = s[tid] - v;  // exclusive
    if (tid == 255) g_blocksum[blockIdx.x] = s[255];
}

__global__ void k_scan2() {
    if (threadIdx.x == 0) {
        int run = 0;
        for (int b = 0; b < SCAN_NB; b++) {
            int t = g_blocksum[b];
            g_blocksum[b] = run;
            run += t;
        }
    }
}

__global__ void k_scan3() {
    int i = blockIdx.x * blockDim.x + threadIdx.x;
    if (i < N_NODES) {
        int o = g_offsets[i] + g_blocksum[i >> 8];
        g_offsets[i] = o;
        g_cursor[i] = o;
        int d = g_degI[i];
        g_dinv[i] = (d > 0) ? rsqrtf((float)d) : 0.0f;
    }
    if (i == 0) g_offsets[N_NODES] = N_EDGES;
}

__global__ void k_fill(const void* __restrict__ ei) {
    int is64 = g_is64;
    for (int e = blockIdx.x * blockDim.x + threadIdx.x; e < N_EDGES;
         e += gridDim.x * blockDim.x) {
        int r, c;
        edge_rc(ei, is64, e, r, c);
        int p = atomicAdd(&g_cursor[c], 1);
        g_erow[p] = r;
    }
}

// ---------------- GEMM: h = fp16( (x @ W^T + b) * dinv[row] ) ----------------
// Block: 128 rows x 128 cols, 512 threads, each thread 8 rows x 4 cols.
// Both shared tiles use stride 132 floats (128 entries + 4 pad).
__global__ void k_gemm(const float* __restrict__ x, const float* __restrict__ W,
                       const float* __restrict__ bvec) {
    extern __shared__ float sm[];
    float* Wt = sm;                 // [128][132]  Wt[k*132 + c] = W[c][k]
    float* xs = sm + 128 * 132;     // [128][132]  xs[k*132 + r] = x[row0+r][k]

    const int tid  = threadIdx.x;
    const int row0 = blockIdx.x * 128;

    for (int i = tid; i < 128 * 128; i += 512) {
        int c = i >> 7, k = i & 127;
        Wt[k * 132 + c] = W[i];
    }
    for (int i = tid; i < 128 * 32; i += 512) {
        int r = i >> 5, kq = i & 31;
        int gr = row0 + r;
        float4 v = (gr < N_NODES) ? *(const float4*)&x[(size_t)gr * D + kq * 4]
                                  : make_float4(0.f, 0.f, 0.f, 0.f);
        xs[(kq * 4 + 0) * 132 + r] = v.x;
        xs[(kq * 4 + 1) * 132 + r] = v.y;
        xs[(kq * 4 + 2) * 132 + r] = v.z;
        xs[(kq * 4 + 3) * 132 + r] = v.w;
    }
    if (blockIdx.x == 0 && tid < 2 * D) g_stats[tid] = 0.0f;  // zero stats for layer
    __syncthreads();

    const int tx = tid & 31;   // cols 4*tx..4*tx+3
    const int ty = tid >> 5;   // rows 8*ty..8*ty+7  (ty in 0..15)

    float4 bv = *(const float4*)&bvec[4 * tx];
    float4 acc[8];
#pragma unroll
    for (int rr = 0; rr < 8; rr++) acc[rr] = bv;

#pragma unroll 8
    for (int k = 0; k < 128; k++) {
        float4 w  = *(float4*)&Wt[k * 132 + 4 * tx];
        float4 xa = *(float4*)&xs[k * 132 + 8 * ty];
        float4 xb = *(float4*)&xs[k * 132 + 8 * ty + 4];
        float xr[8] = {xa.x, xa.y, xa.z, xa.w, xb.x, xb.y, xb.z, xb.w};
#pragma unroll
        for (int rr = 0; rr < 8; rr++) {
            acc[rr].x += xr[rr] * w.x;
            acc[rr].y += xr[rr] * w.y;
            acc[rr].z += xr[rr] * w.z;
            acc[rr].w += xr[rr] * w.w;
        }
    }

#pragma unroll
    for (int rr = 0; rr < 8; rr++) {
        int r = row0 + ty * 8 + rr;
        if (r < N_NODES) {
            float s = g_dinv[r];
            __half2 p0 = __floats2half2_rn(acc[rr].x * s, acc[rr].y * s);
            __half2 p1 = __floats2half2_rn(acc[rr].z * s, acc[rr].w * s);
            uint2 pk;
            pk.x = *reinterpret_cast<unsigned*>(&p0);
            pk.y = *reinterpret_cast<unsigned*>(&p1);
            g_h[(size_t)r * 32 + tx] = pk;
        }
    }
}

// ---------------- gather: agg[n] = dinv[n] * sum_{e: col=n} h[row_e]; fused BN stats ----------------
__global__ void k_gather() {
    const int lane = threadIdx.x & 31;
    const int warp = threadIdx.x >> 5;
    const int gw   = blockIdx.x * 8 + warp;
    const int nw   = gridDim.x * 8;
    const uint2* __restrict__ hp = g_h;   // 8B per lane = 4 fp16 cols
    float4* ap = (float4*)g_agg;

    float s0 = 0.f, s1 = 0.f, s2 = 0.f, s3 = 0.f;
    float q0 = 0.f, q1 = 0.f, q2 = 0.f, q3 = 0.f;

    for (int node = gw; node < N_NODES; node += nw) {
        int st = g_offsets[node];
        int en = g_offsets[node + 1];
        float4 acc = make_float4(0.f, 0.f, 0.f, 0.f);
        for (int i = st; i < en; i += 32) {
            int idx = 0;
            if (i + lane < en) idx = g_erow[i + lane];
            int n = min(32, en - i);
#pragma unroll 4
            for (int j = 0; j < n; j++) {
                int r = __shfl_sync(0xffffffffu, idx, j);
                uint2 v = hp[(size_t)r * 32 + lane];
                __half2 a = *reinterpret_cast<__half2*>(&v.x);
                __half2 b = *reinterpret_cast<__half2*>(&v.y);
                float2 f0 = __half22float2(a);
                float2 f1 = __half22float2(b);
                acc.x += f0.x; acc.y += f0.y; acc.z += f1.x; acc.w += f1.y;
            }
        }
        float dc = g_dinv[node];
        acc.x *= dc; acc.y *= dc; acc.z *= dc; acc.w *= dc;
        ap[node * 32 + lane] = acc;
        s0 += acc.x; s1 += acc.y; s2 += acc.z; s3 += acc.w;
        q0 += acc.x * acc.x; q1 += acc.y * acc.y;
        q2 += acc.z * acc.z; q3 += acc.w * acc.w;
    }

    // block-level stat reduction: shared atomics, then one global atomic per column
    __shared__ float ssum[128], ssq[128];
    if (threadIdx.x < 128) { ssum[threadIdx.x] = 0.f; ssq[threadIdx.x] = 0.f; }
    __syncthreads();
    int c = lane * 4;
    atomicAdd(&ssum[c + 0], s0); atomicAdd(&ssum[c + 1], s1);
    atomicAdd(&ssum[c + 2], s2); atomicAdd(&ssum[c + 3], s3);
    atomicAdd(&ssq[c + 0], q0); atomicAdd(&ssq[c + 1], q1);
    atomicAdd(&ssq[c + 2], q2); atomicAdd(&ssq[c + 3], q3);
    __syncthreads();
    if (threadIdx.x < 128) {
        atomicAdd(&g_stats[threadIdx.x], ssum[threadIdx.x]);
        atomicAdd(&g_stats[D + threadIdx.x], ssq[threadIdx.x]);
    }
}

__global__ void k_bnfinal(const float* __restrict__ gamma, const float* __restrict__ beta) {
    int c = threadIdx.x;
    const float inv_n = 1.0f / (float)N_NODES;
    float mu  = g_stats[c] * inv_n;
    float var = g_stats[D + c] * inv_n - mu * mu;
    float sc  = gamma[c] * rsqrtf(var + BN_EPS);
    g_bn[c]     = sc;
    g_bn[D + c] = beta[c] - mu * sc;
}

// ---------------- apply: x_new = x + relu(agg*scale + shift) ----------------
__global__ void k_apply(const float* __restrict__ xsrc, float* __restrict__ xdst) {
    int i = blockIdx.x * blockDim.x + threadIdx.x;  // over N*D/4 float4s
    if (i >= N_NODES * 32) return;
    int cq = i & 31;
    float4 a  = ((const float4*)g_agg)[i];
    float4 xv = ((const float4*)xsrc)[i];
    float4 sc = ((const float4*)g_bn)[cq];
    float4 sh = ((const float4*)(g_bn + D))[cq];
    float4 o;
    o.x = xv.x + fmaxf(fmaf(a.x, sc.x, sh.x), 0.f);
    o.y = xv.y + fmaxf(fmaf(a.y, sc.y, sh.y), 0.f);
    o.z = xv.z + fmaxf(fmaf(a.z, sc.z, sh.z), 0.f);
    o.w = xv.w + fmaxf(fmaf(a.w, sc.w, sh.w), 0.f);
    ((float4*)xdst)[i] = o;
}

// ---------------- launch ----------------
extern "C" void kernel_launch(void* const* d_in, const int* in_sizes, int n_in,
                              void* d_out, int out_size) {
    const float* x     = (const float*)d_in[0];
    const void*  ei    = d_in[1];
    const float* W     = (const float*)d_in[2];
    const float* bvec  = (const float*)d_in[3];
    const float* gamma = (const float*)d_in[4];
    const float* beta  = (const float*)d_in[5];
    float* out = (float*)d_out;

    const size_t smem = (size_t)(2 * 128 * 132) * sizeof(float);  // 132 KB
    cudaFuncSetAttribute(k_gemm, cudaFuncAttributeMaxDynamicSharedMemorySize, (int)smem);

    // preprocessing: zero+detect, degrees, scan(+dinv), CSR fill
    k_pre<<<160, 256>>>((const unsigned long long*)ei);
    k_hist<<<1024, 256>>>(ei);
    k_scan1<<<SCAN_NB, 256>>>();
    k_scan2<<<1, 32>>>();
    k_scan3<<<(N_NODES + 255) / 256, 256>>>();
    k_fill<<<1024, 256>>>(ei);

    const float* xin = x;
    const int gemm_blocks  = (N_NODES + 127) / 128;         // 391
    const int apply_blocks = (N_NODES * 32 + 255) / 256;    // 6250

    for (int l = 0; l < NL; l++) {
        k_gemm<<<gemm_blocks, 512, smem>>>(xin, W + (size_t)l * D * D, bvec + l * D);
        k_gather<<<512, 256>>>();
        k_bnfinal<<<1, 128>>>(gamma + l * D, beta + l * D);
        k_apply<<<apply_blocks, 256>>>(xin, out);
        xin = out;
    }
}